// round 3
// baseline (speedup 1.0000x reference)
#include <cuda_runtime.h>

#define BB 8
#define NN 4096
#define SS 1024
#define KK 32
#define M_TOTAL (BB*SS*KK)   // 262144

// ---------------- device scratch ----------------
__device__ float g_newxyz[BB*SS*3];          // (B,S,3)
__device__ int   g_ballidx[BB*SS*KK];        // (B,S,K)
__device__ float g_X0[67*M_TOTAL];
__device__ float g_Y0[64*M_TOTAL];
__device__ float g_Y1[64*M_TOTAL];
__device__ float g_Y2[128*M_TOTAL];
__device__ float g_sum0[64], g_sq0[64], g_sum1[64], g_sq1[64], g_sum2[128], g_sq2[128];
__device__ float g_a0[64],  g_c0[64],  g_a1[64],  g_c1[64],  g_a2[128],  g_c2[128];

// ---------------- zero stats ----------------
__global__ void zero_stats_kernel() {
    int t = threadIdx.x;
    if (t < 64)  { g_sum0[t]=0.f; g_sq0[t]=0.f; g_sum1[t]=0.f; g_sq1[t]=0.f; }
    if (t < 128) { g_sum2[t]=0.f; g_sq2[t]=0.f; }
}

// ---------------- FPS ----------------
// one block per batch, 1024 threads, 4 points/thread (i = tid + j*1024)
__global__ void __launch_bounds__(1024) fps_kernel(const float* __restrict__ xyz,
                                                   float* __restrict__ out_newxyz_T)
{
    const int b = blockIdx.x;
    const int tid = threadIdx.x;
    const int lane = tid & 31, wid = tid >> 5;
    __shared__ unsigned long long wb[32];
    __shared__ float sc[3];

    const float* xb = xyz + (size_t)b*3*NN;
    float px[4], py[4], pz[4], dmin[4];
#pragma unroll
    for (int j = 0; j < 4; ++j) {
        int i = tid + (j << 10);
        px[j] = xb[i]; py[j] = xb[NN + i]; pz[j] = xb[2*NN + i];
        dmin[j] = 1e10f;
    }
    if (tid == 0) {
        sc[0] = px[0]; sc[1] = py[0]; sc[2] = pz[0];
        int o3 = (b*SS + 0)*3;
        g_newxyz[o3+0] = px[0]; g_newxyz[o3+1] = py[0]; g_newxyz[o3+2] = pz[0];
        out_newxyz_T[(b*3+0)*SS + 0] = px[0];
        out_newxyz_T[(b*3+1)*SS + 0] = py[0];
        out_newxyz_T[(b*3+2)*SS + 0] = pz[0];
    }
    __syncthreads();

    for (int it = 1; it < SS; ++it) {
        const float cx = sc[0], cy = sc[1], cz = sc[2];
        unsigned long long best = 0ull;
#pragma unroll
        for (int j = 0; j < 4; ++j) {
            // exact XLA order: ((dx*dx + dy*dy) + dz*dz), no FMA contraction
            float dx = __fsub_rn(px[j], cx);
            float dy = __fsub_rn(py[j], cy);
            float dz = __fsub_rn(pz[j], cz);
            float d  = __fadd_rn(__fadd_rn(__fmul_rn(dx,dx), __fmul_rn(dy,dy)), __fmul_rn(dz,dz));
            dmin[j] = fminf(dmin[j], d);
            unsigned long long key =
                ((unsigned long long)__float_as_uint(dmin[j]) << 32) |
                (unsigned)(~(unsigned)(tid + (j << 10)));
            if (key > best) best = key;
        }
#pragma unroll
        for (int o = 16; o > 0; o >>= 1) {
            unsigned long long other = __shfl_down_sync(0xffffffffu, best, o);
            if (other > best) best = other;
        }
        if (lane == 0) wb[wid] = best;
        __syncthreads();
        unsigned long long v = wb[lane];
#pragma unroll
        for (int o = 16; o > 0; o >>= 1) {
            unsigned long long other = __shfl_xor_sync(0xffffffffu, v, o);
            if (other > v) v = other;
        }
        int far = (int)(~(unsigned)v);
        if (tid == (far & 1023)) {
            int j = far >> 10;
            sc[0] = px[j]; sc[1] = py[j]; sc[2] = pz[j];
            int o3 = (b*SS + it)*3;
            g_newxyz[o3+0] = px[j]; g_newxyz[o3+1] = py[j]; g_newxyz[o3+2] = pz[j];
            out_newxyz_T[(b*3+0)*SS + it] = px[j];
            out_newxyz_T[(b*3+1)*SS + it] = py[j];
            out_newxyz_T[(b*3+2)*SS + it] = pz[j];
        }
        __syncthreads();
    }
}

// ---------------- ball query ----------------
// one warp per center (b,s), first 32 in-radius indices in ascending order
__global__ void __launch_bounds__(256) ball_kernel(const float* __restrict__ xyz)
{
    const int w = (blockIdx.x * blockDim.x + threadIdx.x) >> 5;
    const int lane = threadIdx.x & 31;
    if (w >= BB*SS) return;
    const int b = w >> 10;

    const float cx = g_newxyz[w*3+0], cy = g_newxyz[w*3+1], cz = g_newxyz[w*3+2];
    const float s2 = __fadd_rn(__fadd_rn(__fmul_rn(cx,cx), __fmul_rn(cy,cy)), __fmul_rn(cz,cz));
    const float R2 = (float)(0.4*0.4);
    const float* xb = xyz + (size_t)b*3*NN;
    int total = 0, firstn = 0;
    int* outp = g_ballidx + w*KK;

    for (int base = 0; base < NN; base += 32) {
        int n = base + lane;
        float px = __ldg(xb + n), py = __ldg(xb + NN + n), pz = __ldg(xb + 2*NN + n);
        float n2  = __fadd_rn(__fadd_rn(__fmul_rn(px,px), __fmul_rn(py,py)), __fmul_rn(pz,pz));
        float dot = __fadd_rn(__fadd_rn(__fmul_rn(cx,px), __fmul_rn(cy,py)), __fmul_rn(cz,pz));
        float d   = __fadd_rn(__fadd_rn(__fmul_rn(-2.0f, dot), s2), n2);
        bool pred = !(d > R2);
        unsigned mask = __ballot_sync(0xffffffffu, pred);
        if (mask) {
            if (total == 0) firstn = base + __ffs(mask) - 1;
            if (pred) {
                int pos = total + __popc(mask & ((1u << lane) - 1u));
                if (pos < KK) outp[pos] = n;
            }
            total += __popc(mask);
            if (total >= KK) break;
        }
    }
    for (int p = total + lane; p < KK; p += 32) outp[p] = firstn;
}

// ---------------- gather / concat -> X0 (67, M) ----------------
__global__ void __launch_bounds__(128) gather_kernel(const float* __restrict__ xyz,
                                                     const float* __restrict__ points)
{
    const int bs = blockIdx.x;            // 0..8191
    const int b = bs >> 10;
    const int tid = threadIdx.x;
    __shared__ int sidx[KK];
    __shared__ float sc[3];
    if (tid < KK) sidx[tid] = g_ballidx[bs*KK + tid];
    if (tid < 3)  sc[tid]   = g_newxyz[bs*3 + tid];
    __syncthreads();

    const size_t m0 = (size_t)bs * KK;
    if (tid < 96) {
        int c = tid >> 5, k = tid & 31;
        float v = __fsub_rn(__ldg(&xyz[((size_t)b*3 + c)*NN + sidx[k]]), sc[c]);
        g_X0[(size_t)c*M_TOTAL + m0 + k] = v;
    }
    const int k = tid & 31, d0 = tid >> 5;   // d0 in 0..3
    const float* pb = points + (size_t)b*64*NN + sidx[k];
#pragma unroll
    for (int i = 0; i < 16; ++i) {
        int d = 4*i + d0;
        g_X0[(size_t)(3+d)*M_TOTAL + m0 + k] = __ldg(pb + (size_t)d*NN);
    }
}

// ---------------- GEMM + bias + stats (+ fused BN/ReLU on input load) ----------------
template<int CIN, int COUT, bool APPLY>
__global__ void __launch_bounds__(256) gemm_kernel(const float* __restrict__ W,
                                                   const float* __restrict__ bias)
{
    constexpr int LAYER = (CIN == 67) ? 0 : ((COUT == 64) ? 1 : 2);
    const float* Xg = (LAYER==0) ? g_X0 : ((LAYER==1) ? g_Y0 : g_Y1);
    float* Yg       = (LAYER==0) ? g_Y0 : ((LAYER==1) ? g_Y1 : g_Y2);
    float* sumArr   = (LAYER==0) ? g_sum0 : ((LAYER==1) ? g_sum1 : g_sum2);
    float* sqArr    = (LAYER==0) ? g_sq0  : ((LAYER==1) ? g_sq1  : g_sq2);
    const float* aPrev = (LAYER==1) ? g_a0 : g_a1;
    const float* cPrev = (LAYER==1) ? g_c0 : g_c1;

    extern __shared__ float smem[];
    float* Xs  = smem;                 // CIN*128
    float* Ws  = Xs + CIN*128;         // COUT*CIN
    float* as_ = Ws + COUT*CIN;        // CIN
    float* cs_ = as_ + CIN;            // CIN

    const int tid = threadIdx.x;
    const int m0 = blockIdx.x * 128;

    if (APPLY) {
        for (int i = tid; i < CIN; i += 256) { as_[i] = aPrev[i]; cs_[i] = cPrev[i]; }
        __syncthreads();
    }
    for (int i = tid; i < CIN*32; i += 256) {
        int c = i >> 5, q = i & 31;
        float4 v = __ldg((const float4*)(Xg + (size_t)c*M_TOTAL + m0) + q);
        if (APPLY) {
            float a = as_[c], cc = cs_[c];
            v.x = fmaxf(0.f, __fmaf_rn(v.x, a, cc));
            v.y = fmaxf(0.f, __fmaf_rn(v.y, a, cc));
            v.z = fmaxf(0.f, __fmaf_rn(v.z, a, cc));
            v.w = fmaxf(0.f, __fmaf_rn(v.w, a, cc));
        }
        *(float4*)(Xs + c*128 + q*4) = v;
    }
    for (int i = tid; i < COUT*CIN; i += 256) Ws[i] = __ldg(W + i);
    __syncthreads();

    const int tx = tid & 15, ty = tid >> 4;
    constexpr int RPT = COUT / 16;
    const int colb = tx * 8;
    const int rowb = ty * RPT;
    float acc[RPT][8];
#pragma unroll
    for (int r = 0; r < RPT; ++r)
#pragma unroll
        for (int j = 0; j < 8; ++j) acc[r][j] = 0.f;

#pragma unroll 4
    for (int c = 0; c < CIN; ++c) {
        float4 x0 = *(const float4*)(Xs + c*128 + colb);
        float4 x1 = *(const float4*)(Xs + c*128 + colb + 4);
        float xv[8] = {x0.x,x0.y,x0.z,x0.w,x1.x,x1.y,x1.z,x1.w};
#pragma unroll
        for (int r = 0; r < RPT; ++r) {
            float wv = Ws[(rowb + r)*CIN + c];
#pragma unroll
            for (int j = 0; j < 8; ++j) acc[r][j] = __fmaf_rn(wv, xv[j], acc[r][j]);
        }
    }

#pragma unroll
    for (int r = 0; r < RPT; ++r) {
        int ch = rowb + r;
        float bv = __ldg(bias + ch);
        float o[8];
        float s = 0.f, s2 = 0.f;
#pragma unroll
        for (int j = 0; j < 8; ++j) {
            o[j] = acc[r][j] + bv;
            s += o[j];
            s2 = __fmaf_rn(o[j], o[j], s2);
        }
        float* yp = Yg + (size_t)ch*M_TOTAL + m0 + colb;
        *(float4*)yp       = make_float4(o[0],o[1],o[2],o[3]);
        *(float4*)(yp + 4) = make_float4(o[4],o[5],o[6],o[7]);
#pragma unroll
        for (int off = 8; off > 0; off >>= 1) {
            s  += __shfl_xor_sync(0xffffffffu, s,  off);
            s2 += __shfl_xor_sync(0xffffffffu, s2, off);
        }
        if (tx == 0) { atomicAdd(sumArr + ch, s); atomicAdd(sqArr + ch, s2); }
    }
}

// ---------------- BN stats finalize ----------------
__global__ void stats_kernel(int layer, const float* __restrict__ g, const float* __restrict__ bt)
{
    int c = threadIdx.x;
    float *sum, *sq, *a, *cc; int C;
    if (layer == 0)      { sum=g_sum0; sq=g_sq0; a=g_a0; cc=g_c0; C=64; }
    else if (layer == 1) { sum=g_sum1; sq=g_sq1; a=g_a1; cc=g_c1; C=64; }
    else                 { sum=g_sum2; sq=g_sq2; a=g_a2; cc=g_c2; C=128; }
    if (c < C) {
        const float invM = 1.0f / (float)M_TOTAL;
        float mean = sum[c] * invM;
        float var  = __fmaf_rn(-mean, mean, sq[c] * invM);
        float inv  = 1.0f / sqrtf(var + 1e-5f);
        float av   = g[c] * inv;
        a[c]  = av;
        cc[c] = __fmaf_rn(-mean, av, bt[c]);
    }
}

// ---------------- BN+ReLU + max-pool over K ----------------
__global__ void __launch_bounds__(256) pool_kernel(float* __restrict__ out)
{
    int gid = blockIdx.x * blockDim.x + threadIdx.x;
    if (gid >= BB*128*SS) return;
    int s = gid & (SS-1);
    int o = (gid >> 10) & 127;
    int b = gid >> 17;
    float a = g_a2[o], c = g_c2[o];
    const float4* y = (const float4*)(g_Y2 + (size_t)o*M_TOTAL + ((size_t)((b<<10) | s) << 5));
    float m = 0.f;
#pragma unroll
    for (int q = 0; q < 8; ++q) {
        float4 v = __ldg(y + q);
        m = fmaxf(m, fmaxf(0.f, __fmaf_rn(v.x, a, c)));
        m = fmaxf(m, fmaxf(0.f, __fmaf_rn(v.y, a, c)));
        m = fmaxf(m, fmaxf(0.f, __fmaf_rn(v.z, a, c)));
        m = fmaxf(m, fmaxf(0.f, __fmaf_rn(v.w, a, c)));
    }
    out[(size_t)((b*128 + o) << 10) + s] = m;
}

// ---------------- launch ----------------
extern "C" void kernel_launch(void* const* d_in, const int* in_sizes, int n_in,
                              void* d_out, int out_size)
{
    const float* xyz    = (const float*)d_in[0];
    const float* points = (const float*)d_in[1];
    const float* W0  = (const float*)d_in[2];
    const float* b0  = (const float*)d_in[3];
    const float* g0  = (const float*)d_in[4];
    const float* bt0 = (const float*)d_in[5];
    const float* W1  = (const float*)d_in[6];
    const float* b1  = (const float*)d_in[7];
    const float* g1  = (const float*)d_in[8];
    const float* bt1 = (const float*)d_in[9];
    const float* W2  = (const float*)d_in[10];
    const float* b2  = (const float*)d_in[11];
    const float* g2  = (const float*)d_in[12];
    const float* bt2 = (const float*)d_in[13];

    float* out = (float*)d_out;
    float* out_feat = out + BB*3*SS;

    const int sm0 = (67*128 + 64*67  + 2*67 ) * 4;
    const int sm1 = (64*128 + 64*64  + 2*64 ) * 4;
    const int sm2 = (64*128 + 128*64 + 2*64 ) * 4;
    cudaFuncSetAttribute(gemm_kernel<67,64,false>, cudaFuncAttributeMaxDynamicSharedMemorySize, sm0);
    cudaFuncSetAttribute(gemm_kernel<64,64,true >, cudaFuncAttributeMaxDynamicSharedMemorySize, sm1);
    cudaFuncSetAttribute(gemm_kernel<64,128,true>, cudaFuncAttributeMaxDynamicSharedMemorySize, sm2);

    zero_stats_kernel<<<1, 128>>>();
    fps_kernel<<<BB, 1024>>>(xyz, out);
    ball_kernel<<<(BB*SS)/8, 256>>>(xyz);
    gather_kernel<<<BB*SS, 128>>>(xyz, points);

    gemm_kernel<67,64,false><<<M_TOTAL/128, 256, sm0>>>(W0, b0);
    stats_kernel<<<1, 128>>>(0, g0, bt0);
    gemm_kernel<64,64,true ><<<M_TOTAL/128, 256, sm1>>>(W1, b1);
    stats_kernel<<<1, 128>>>(1, g1, bt1);
    gemm_kernel<64,128,true><<<M_TOTAL/128, 256, sm2>>>(W2, b2);
    stats_kernel<<<1, 128>>>(2, g2, bt2);

    pool_kernel<<<(BB*128*SS)/256, 256>>>(out_feat);
}

// round 4
// speedup vs baseline: 1.3181x; 1.3181x over previous
#include <cuda_runtime.h>

#define BB 8
#define NN 4096
#define SS 1024
#define KK 32
#define M_TOTAL (BB*SS*KK)   // 262144
#define NBS (BB*SS)          // 8192

// ---------------- device scratch ----------------
__device__ float g_newxyz[NBS*3];            // (B,S,3)
__device__ int   g_ballidx[NBS*KK];          // (B,S,K)
__device__ float g_X0[67*M_TOTAL];
__device__ float g_Y0[64*M_TOTAL];
__device__ float g_Y1[64*M_TOTAL];
__device__ float g_mx2[128*NBS];             // per (ch, b*1024+s) max of raw gemm2 output over K
__device__ float g_mn2[128*NBS];             // min
__device__ float g_sum0[64], g_sq0[64], g_sum1[64], g_sq1[64], g_sum2[128], g_sq2[128];
__device__ float g_a0[64],  g_c0[64],  g_a1[64],  g_c1[64],  g_a2[128],  g_c2[128];

// ---------------- zero stats ----------------
__global__ void zero_stats_kernel() {
    int t = threadIdx.x;
    if (t < 64)  { g_sum0[t]=0.f; g_sq0[t]=0.f; g_sum1[t]=0.f; g_sq1[t]=0.f; }
    if (t < 128) { g_sum2[t]=0.f; g_sq2[t]=0.f; }
}

// ---------------- FPS ----------------
// one block per batch, 1024 threads, 4 points/thread.
// Single __syncthreads per iteration; REDUX-based argmax; center re-read via L1
// broadcast __ldg; per-warp results double-buffered to avoid a second barrier.
__global__ void __launch_bounds__(1024) fps_kernel(const float* __restrict__ xyz,
                                                   float* __restrict__ out_newxyz_T)
{
    const int b = blockIdx.x;
    const int tid = threadIdx.x;
    const int lane = tid & 31, wid = tid >> 5;
    __shared__ unsigned sd[2][32];
    __shared__ unsigned si[2][32];

    const float* xb = xyz + (size_t)b*3*NN;
    float px[4], py[4], pz[4], dmin[4];
#pragma unroll
    for (int j = 0; j < 4; ++j) {
        int i = tid + (j << 10);
        px[j] = xb[i]; py[j] = xb[NN + i]; pz[j] = xb[2*NN + i];
        dmin[j] = 1e10f;
    }
    // iteration 0: farthest = 0, center = point 0
    float cx = __ldg(xb + 0), cy = __ldg(xb + NN), cz = __ldg(xb + 2*NN);
    if (tid == 0) {
        int o3 = (b*SS + 0)*3;
        g_newxyz[o3+0] = cx; g_newxyz[o3+1] = cy; g_newxyz[o3+2] = cz;
        out_newxyz_T[(b*3+0)*SS + 0] = cx;
        out_newxyz_T[(b*3+1)*SS + 0] = cy;
        out_newxyz_T[(b*3+2)*SS + 0] = cz;
    }

    for (int it = 1; it < SS; ++it) {
        unsigned long long best = 0ull;
#pragma unroll
        for (int j = 0; j < 4; ++j) {
            // exact XLA order: ((dx*dx + dy*dy) + dz*dz), no FMA contraction
            float dx = __fsub_rn(px[j], cx);
            float dy = __fsub_rn(py[j], cy);
            float dz = __fsub_rn(pz[j], cz);
            float d  = __fadd_rn(__fadd_rn(__fmul_rn(dx,dx), __fmul_rn(dy,dy)), __fmul_rn(dz,dz));
            dmin[j] = fminf(dmin[j], d);
            unsigned long long key =
                ((unsigned long long)__float_as_uint(dmin[j]) << 32) |
                (unsigned)(~(unsigned)(tid + (j << 10)));
            if (key > best) best = key;
        }
        unsigned db  = (unsigned)(best >> 32);
        unsigned idx = ~(unsigned)best;
        unsigned wd = __reduce_max_sync(0xffffffffu, db);
        unsigned wi = __reduce_min_sync(0xffffffffu, (db == wd) ? idx : 0xffffffffu);
        int buf = it & 1;
        if (lane == 0) { sd[buf][wid] = wd; si[buf][wid] = wi; }
        __syncthreads();
        unsigned d2 = sd[buf][lane], i2 = si[buf][lane];
        unsigned gd  = __reduce_max_sync(0xffffffffu, d2);
        unsigned far = __reduce_min_sync(0xffffffffu, (d2 == gd) ? i2 : 0xffffffffu);
        // everyone fetches the new center (L1 broadcast)
        cx = __ldg(xb + far); cy = __ldg(xb + NN + far); cz = __ldg(xb + 2*NN + far);
        if (tid == (int)(far & 1023u)) {
            int o3 = (b*SS + it)*3;
            g_newxyz[o3+0] = cx; g_newxyz[o3+1] = cy; g_newxyz[o3+2] = cz;
            out_newxyz_T[(b*3+0)*SS + it] = cx;
            out_newxyz_T[(b*3+1)*SS + it] = cy;
            out_newxyz_T[(b*3+2)*SS + it] = cz;
        }
    }
}

// ---------------- ball query ----------------
// one warp per center (b,s), first 32 in-radius indices in ascending order
__global__ void __launch_bounds__(256) ball_kernel(const float* __restrict__ xyz)
{
    const int w = (blockIdx.x * blockDim.x + threadIdx.x) >> 5;
    const int lane = threadIdx.x & 31;
    if (w >= NBS) return;
    const int b = w >> 10;

    const float cx = g_newxyz[w*3+0], cy = g_newxyz[w*3+1], cz = g_newxyz[w*3+2];
    const float s2 = __fadd_rn(__fadd_rn(__fmul_rn(cx,cx), __fmul_rn(cy,cy)), __fmul_rn(cz,cz));
    const float R2 = (float)(0.4*0.4);
    const float* xb = xyz + (size_t)b*3*NN;
    int total = 0, firstn = 0;
    int* outp = g_ballidx + w*KK;

    for (int base = 0; base < NN; base += 32) {
        int n = base + lane;
        float px = __ldg(xb + n), py = __ldg(xb + NN + n), pz = __ldg(xb + 2*NN + n);
        float n2  = __fadd_rn(__fadd_rn(__fmul_rn(px,px), __fmul_rn(py,py)), __fmul_rn(pz,pz));
        float dot = __fadd_rn(__fadd_rn(__fmul_rn(cx,px), __fmul_rn(cy,py)), __fmul_rn(cz,pz));
        float d   = __fadd_rn(__fadd_rn(__fmul_rn(-2.0f, dot), s2), n2);
        bool pred = !(d > R2);
        unsigned mask = __ballot_sync(0xffffffffu, pred);
        if (mask) {
            if (total == 0) firstn = base + __ffs(mask) - 1;
            if (pred) {
                int pos = total + __popc(mask & ((1u << lane) - 1u));
                if (pos < KK) outp[pos] = n;
            }
            total += __popc(mask);
            if (total >= KK) break;
        }
    }
    for (int p = total + lane; p < KK; p += 32) outp[p] = firstn;
}

// ---------------- gather / concat -> X0 (67, M) ----------------
__global__ void __launch_bounds__(128) gather_kernel(const float* __restrict__ xyz,
                                                     const float* __restrict__ points)
{
    const int bs = blockIdx.x;            // 0..8191
    const int b = bs >> 10;
    const int tid = threadIdx.x;
    __shared__ int sidx[KK];
    __shared__ float sc[3];
    if (tid < KK) sidx[tid] = g_ballidx[bs*KK + tid];
    if (tid < 3)  sc[tid]   = g_newxyz[bs*3 + tid];
    __syncthreads();

    const size_t m0 = (size_t)bs * KK;
    if (tid < 96) {
        int c = tid >> 5, k = tid & 31;
        float v = __fsub_rn(__ldg(&xyz[((size_t)b*3 + c)*NN + sidx[k]]), sc[c]);
        g_X0[(size_t)c*M_TOTAL + m0 + k] = v;
    }
    const int k = tid & 31, d0 = tid >> 5;   // d0 in 0..3
    const float* pb = points + (size_t)b*64*NN + sidx[k];
#pragma unroll
    for (int i = 0; i < 16; ++i) {
        int d = 4*i + d0;
        g_X0[(size_t)(3+d)*M_TOTAL + m0 + k] = __ldg(pb + (size_t)d*NN);
    }
}

// ---------------- GEMM + bias + stats (+ fused BN/ReLU on load; layer2 fuses pool) ----------------
template<int CIN, int COUT, int LAYER>
__global__ void __launch_bounds__(256) gemm_kernel(const float* __restrict__ W,
                                                   const float* __restrict__ bias)
{
    const float* Xg = (LAYER==0) ? g_X0 : ((LAYER==1) ? g_Y0 : g_Y1);
    float* Yg       = (LAYER==0) ? g_Y0 : g_Y1;           // unused for LAYER==2
    float* sumArr   = (LAYER==0) ? g_sum0 : ((LAYER==1) ? g_sum1 : g_sum2);
    float* sqArr    = (LAYER==0) ? g_sq0  : ((LAYER==1) ? g_sq1  : g_sq2);
    const float* aPrev = (LAYER==1) ? g_a0 : g_a1;
    const float* cPrev = (LAYER==1) ? g_c0 : g_c1;

    extern __shared__ float smem[];
    float* Xs  = smem;                  // CIN * 128
    float* WsT = Xs + CIN*128;          // [c][o] transposed weights
    float* as_ = WsT + CIN*COUT;        // CIN
    float* cs_ = as_ + CIN;             // CIN

    const int tid = threadIdx.x;
    const int m0  = blockIdx.x * 128;

    if (LAYER >= 1) {
        for (int i = tid; i < CIN; i += 256) { as_[i] = aPrev[i]; cs_[i] = cPrev[i]; }
        __syncthreads();
    }
    // X tile (with fused BN+ReLU of previous layer)
    for (int i = tid; i < CIN*32; i += 256) {
        int c = i >> 5, q = i & 31;
        float4 v = __ldg((const float4*)(Xg + (size_t)c*M_TOTAL + m0) + q);
        if (LAYER >= 1) {
            float a = as_[c], cc = cs_[c];
            v.x = fmaxf(0.f, __fmaf_rn(v.x, a, cc));
            v.y = fmaxf(0.f, __fmaf_rn(v.y, a, cc));
            v.z = fmaxf(0.f, __fmaf_rn(v.z, a, cc));
            v.w = fmaxf(0.f, __fmaf_rn(v.w, a, cc));
        }
        *(float4*)(Xs + c*128 + (q << 2)) = v;
    }
    // W transposed into smem: WsT[c*COUT + o]
    for (int i = tid; i < COUT*CIN; i += 256) {
        int o = i / CIN, c = i - o*CIN;
        WsT[c*COUT + o] = __ldg(W + i);
    }
    __syncthreads();

    const int tx = tid & 15, ty = tid >> 4;
    constexpr int RPT = COUT / 16;
    const int colb = tx << 3;
    const int rowb = ty * RPT;
    float acc[RPT][8];
#pragma unroll
    for (int r = 0; r < RPT; ++r)
#pragma unroll
        for (int j = 0; j < 8; ++j) acc[r][j] = 0.f;

#pragma unroll 4
    for (int c = 0; c < CIN; ++c) {
        float4 x0 = *(const float4*)(Xs + c*128 + colb);
        float4 x1 = *(const float4*)(Xs + c*128 + colb + 4);
        float xv[8] = {x0.x,x0.y,x0.z,x0.w,x1.x,x1.y,x1.z,x1.w};
        const float4* wp = (const float4*)(WsT + c*COUT + rowb);
#pragma unroll
        for (int rq = 0; rq < RPT/4; ++rq) {
            float4 w4 = wp[rq];
            float wv[4] = {w4.x, w4.y, w4.z, w4.w};
#pragma unroll
            for (int r4 = 0; r4 < 4; ++r4)
#pragma unroll
                for (int j = 0; j < 8; ++j)
                    acc[rq*4 + r4][j] = __fmaf_rn(wv[r4], xv[j], acc[rq*4 + r4][j]);
        }
    }

#pragma unroll
    for (int r = 0; r < RPT; ++r) {
        int ch = rowb + r;
        float bv = __ldg(bias + ch);
        float o[8];
        float s = 0.f, s2 = 0.f;
#pragma unroll
        for (int j = 0; j < 8; ++j) {
            o[j] = acc[r][j] + bv;
            s += o[j];
            s2 = __fmaf_rn(o[j], o[j], s2);
        }
        if (LAYER < 2) {
            float* yp = Yg + (size_t)ch*M_TOTAL + m0 + colb;
            *(float4*)yp       = make_float4(o[0],o[1],o[2],o[3]);
            *(float4*)(yp + 4) = make_float4(o[4],o[5],o[6],o[7]);
        } else {
            // fused max-pool over K: this thread's 8 cols are inside one k-group (tx>>2)
            float mx = o[0], mn = o[0];
#pragma unroll
            for (int j = 1; j < 8; ++j) { mx = fmaxf(mx, o[j]); mn = fminf(mn, o[j]); }
            mx = fmaxf(mx, __shfl_xor_sync(0xffffffffu, mx, 1));
            mx = fmaxf(mx, __shfl_xor_sync(0xffffffffu, mx, 2));
            mn = fminf(mn, __shfl_xor_sync(0xffffffffu, mn, 1));
            mn = fminf(mn, __shfl_xor_sync(0xffffffffu, mn, 2));
            if ((tx & 3) == 0) {
                int bs = (m0 >> 5) + (tx >> 2);
                g_mx2[ch*NBS + bs] = mx;
                g_mn2[ch*NBS + bs] = mn;
            }
        }
#pragma unroll
        for (int off = 8; off > 0; off >>= 1) {
            s  += __shfl_xor_sync(0xffffffffu, s,  off);
            s2 += __shfl_xor_sync(0xffffffffu, s2, off);
        }
        if (tx == 0) { atomicAdd(sumArr + ch, s); atomicAdd(sqArr + ch, s2); }
    }
}

// ---------------- BN stats finalize ----------------
__global__ void stats_kernel(int layer, const float* __restrict__ g, const float* __restrict__ bt)
{
    int c = threadIdx.x;
    float *sum, *sq, *a, *cc; int C;
    if (layer == 0)      { sum=g_sum0; sq=g_sq0; a=g_a0; cc=g_c0; C=64; }
    else if (layer == 1) { sum=g_sum1; sq=g_sq1; a=g_a1; cc=g_c1; C=64; }
    else                 { sum=g_sum2; sq=g_sq2; a=g_a2; cc=g_c2; C=128; }
    if (c < C) {
        const float invM = 1.0f / (float)M_TOTAL;
        float mean = sum[c] * invM;
        float var  = __fmaf_rn(-mean, mean, sq[c] * invM);
        float inv  = 1.0f / sqrtf(var + 1e-5f);
        float av   = g[c] * inv;
        a[c]  = av;
        cc[c] = __fmaf_rn(-mean, av, bt[c]);
    }
}

// ---------------- finalize: BN+ReLU on pooled extrema ----------------
// max_k relu(a*y+c) == relu(a*(a>=0 ? max_k y : min_k y) + c)  (bitwise; fmaf monotone in y)
__global__ void __launch_bounds__(256) finalize_kernel(float* __restrict__ out)
{
    int gid = blockIdx.x * blockDim.x + threadIdx.x;
    if (gid >= BB*128*SS) return;
    int s = gid & (SS-1);
    int o = (gid >> 10) & 127;
    int b = gid >> 17;
    float a = g_a2[o], c = g_c2[o];
    int bs = (b << 10) + s;
    float v = (a >= 0.f) ? g_mx2[o*NBS + bs] : g_mn2[o*NBS + bs];
    out[gid] = fmaxf(0.f, __fmaf_rn(v, a, c));
}

// ---------------- launch ----------------
extern "C" void kernel_launch(void* const* d_in, const int* in_sizes, int n_in,
                              void* d_out, int out_size)
{
    const float* xyz    = (const float*)d_in[0];
    const float* points = (const float*)d_in[1];
    const float* W0  = (const float*)d_in[2];
    const float* b0  = (const float*)d_in[3];
    const float* g0  = (const float*)d_in[4];
    const float* bt0 = (const float*)d_in[5];
    const float* W1  = (const float*)d_in[6];
    const float* b1  = (const float*)d_in[7];
    const float* g1  = (const float*)d_in[8];
    const float* bt1 = (const float*)d_in[9];
    const float* W2  = (const float*)d_in[10];
    const float* b2  = (const float*)d_in[11];
    const float* g2  = (const float*)d_in[12];
    const float* bt2 = (const float*)d_in[13];

    float* out = (float*)d_out;
    float* out_feat = out + BB*3*SS;

    const int sm0 = (67*128 + 67*64  + 2*67 ) * 4;
    const int sm1 = (64*128 + 64*64  + 2*64 ) * 4;
    const int sm2 = (64*128 + 64*128 + 2*64 ) * 4;
    cudaFuncSetAttribute(gemm_kernel<67,64,0>,  cudaFuncAttributeMaxDynamicSharedMemorySize, sm0);
    cudaFuncSetAttribute(gemm_kernel<64,64,1>,  cudaFuncAttributeMaxDynamicSharedMemorySize, sm1);
    cudaFuncSetAttribute(gemm_kernel<64,128,2>, cudaFuncAttributeMaxDynamicSharedMemorySize, sm2);

    zero_stats_kernel<<<1, 128>>>();
    fps_kernel<<<BB, 1024>>>(xyz, out);
    ball_kernel<<<(NBS*32)/256, 256>>>(xyz);
    gather_kernel<<<NBS, 128>>>(xyz, points);

    gemm_kernel<67,64,0><<<M_TOTAL/128, 256, sm0>>>(W0, b0);
    stats_kernel<<<1, 128>>>(0, g0, bt0);
    gemm_kernel<64,64,1><<<M_TOTAL/128, 256, sm1>>>(W1, b1);
    stats_kernel<<<1, 128>>>(1, g1, bt1);
    gemm_kernel<64,128,2><<<M_TOTAL/128, 256, sm2>>>(W2, b2);
    stats_kernel<<<1, 128>>>(2, g2, bt2);

    finalize_kernel<<<(BB*128*SS)/256, 256>>>(out_feat);
}